// round 8
// baseline (speedup 1.0000x reference)
#include <cuda_runtime.h>

#define N_PART 512
#define NK 32
#define NT 10
#define NB 8
#define EPSF 1e-6f
#define LOG2E 1.4426950408889634f
#define TWO_LN2 1.3862943611198906f

typedef unsigned long long ull;

// Per-k folded constants: {mu_k, -ig2_k*log2e, w_eff_k, -2*ig2_k*w_eff_k}
__device__ float4 g_cK[NK];
__device__ float g_C;

__device__ __forceinline__ float ex2f(float x) {
    float r; asm("ex2.approx.f32 %0, %1;" : "=f"(r) : "f"(x)); return r;
}
__device__ __forceinline__ float sqrt_ap(float x) {
    float r; asm("sqrt.approx.f32 %0, %1;" : "=f"(r) : "f"(x)); return r;
}
__device__ __forceinline__ ull pk(float lo, float hi) {
    ull r; asm("mov.b64 %0, {%1, %2};" : "=l"(r) : "f"(lo), "f"(hi)); return r;
}
__device__ __forceinline__ void upk(ull v, float& lo, float& hi) {
    asm("mov.b64 {%0, %1}, %2;" : "=f"(lo), "=f"(hi) : "l"(v));
}
__device__ __forceinline__ ull f2add(ull a, ull b) {
    ull r; asm("add.rn.f32x2 %0, %1, %2;" : "=l"(r) : "l"(a), "l"(b)); return r;
}
__device__ __forceinline__ ull f2mul(ull a, ull b) {
    ull r; asm("mul.rn.f32x2 %0, %1, %2;" : "=l"(r) : "l"(a), "l"(b)); return r;
}
__device__ __forceinline__ ull f2fma(ull a, ull b, ull c) {
    ull r; asm("fma.rn.f32x2 %0, %1, %2, %3;" : "=l"(r) : "l"(a), "l"(b), "l"(c)); return r;
}

__global__ void prep_kernel(const float* __restrict__ t,
                            const float* __restrict__ mus,
                            const float* __restrict__ nlg,
                            const float* __restrict__ mus_t,
                            const float* __restrict__ nlg_t,
                            const float* __restrict__ W,
                            const float* __restrict__ bias,
                            const float* __restrict__ imp,
                            float* __restrict__ div_out) {
    __shared__ float strbf[NT];
    int k = threadIdx.x;
    if (k == 0) {
        float tt = t[0];
        float rb[NT];
        float s = 0.f;
        for (int i = 0; i < NT; i++) {
            float g = expf(nlg_t[i]);
            float ig2 = g * g;
            float diff = tt - mus_t[i];
            float e = expf(-diff * diff * ig2);
            rb[i] = e;
            s += e;
        }
        float inv = 1.f / (EPSF + s);
        for (int i = 0; i < NT; i++) strbf[i] = rb[i] * inv;
    }
    __syncthreads();
    float w = 0.f;
    for (int ti = 0; ti < NT; ti++) w += W[k * NT + ti] * strbf[ti];
    float g = expf(nlg[k]);
    float ig2 = g * g;
    g_cK[k] = make_float4(mus[k], -ig2 * LOG2E, w, -2.f * ig2 * w);
    float cp = imp[k] * imp[k] * w;
    #pragma unroll
    for (int o = 16; o > 0; o >>= 1) cp += __shfl_down_sync(0xffffffffu, cp, o);
    if (k == 0) {
        float bb = 0.f;
        for (int ti = 0; ti < NT; ti++) bb += bias[ti] * strbf[ti];
        g_C = bb + cp;
    }
    if (k < NB) div_out[k] = 0.f;
}

__global__ __launch_bounds__(128, 8) void force_kernel(const float* __restrict__ x,
                                                       float* __restrict__ f_out,
                                                       float* __restrict__ div_out) {
    __shared__ float sx[N_PART * 3];
    __shared__ ull sc2[NK * 4];   // per k: {-mu,-mu},{cy,cy},{cz,cz},{cw,cw}
    const int b = blockIdx.y;
    const int tid = threadIdx.x;

    for (int idx = tid; idx < N_PART * 3; idx += 128)
        sx[idx] = x[b * N_PART * 3 + idx];
    if (tid < NK) {
        float4 c = g_cK[tid];
        sc2[tid * 4 + 0] = pk(-c.x, -c.x);
        sc2[tid * 4 + 1] = pk(c.y, c.y);
        sc2[tid * 4 + 2] = pk(c.z, c.z);
        sc2[tid * 4 + 3] = pk(c.w, c.w);
    }
    __syncthreads();

    const float C = g_C;
    const ull C2      = pk(C, C);
    const ull kTLN2   = pk(TWO_LN2, TWO_LN2);
    const ull kM1     = pk(-1.f, -1.f);
    const ull kThree  = pk(3.f, 3.f);
    const int warp = tid >> 5;
    const int lane = tid & 31;
    const int i = blockIdx.x * 4 + warp;

    const float xi0 = sx[i * 3 + 0];
    const float xi1 = sx[i * 3 + 1];
    const float xi2 = sx[i * 3 + 2];

    ull fx2 = 0ull, fy2 = 0ull, fz2 = 0ull, dv2 = 0ull;

    #pragma unroll 1
    for (int jj = 0; jj < 8; jj++) {
        const int j1 = lane + jj * 32;
        const int j2 = j1 + 256;
        const float ax = xi0 - sx[j1 * 3 + 0];
        const float ay = xi1 - sx[j1 * 3 + 1];
        const float az = xi2 - sx[j1 * 3 + 2];
        const float bx = xi0 - sx[j2 * 3 + 0];
        const float by = xi1 - sx[j2 * 3 + 1];
        const float bz = xi2 - sx[j2 * 3 + 2];
        const float da = sqrt_ap(fmaf(ax, ax, fmaf(ay, ay, fmaf(az, az, EPSF))));
        const float db = sqrt_ap(fmaf(bx, bx, fmaf(by, by, fmaf(bz, bz, EPSF))));
        const ull dp  = pk(da, db);
        const ull dxp = pk(ax, bx);
        const ull dyp = pk(ay, by);
        const ull dzp = pk(az, bz);

        ull srbf = 0ull, s1 = 0ull, sd = 0ull, s2 = 0ull;
        #pragma unroll 8
        for (int k = 0; k < NK; k++) {
            ull nmu, cy, cz, cw;
            asm("ld.shared.v2.u64 {%0, %1}, [%2];"
                : "=l"(nmu), "=l"(cy) : "r"((unsigned)(__cvta_generic_to_shared(&sc2[k * 4]))));
            asm("ld.shared.v2.u64 {%0, %1}, [%2];"
                : "=l"(cz), "=l"(cw) : "r"((unsigned)(__cvta_generic_to_shared(&sc2[k * 4 + 2]))));
            const ull diff = f2add(dp, nmu);            // d - mu (both pairs)
            const ull arg  = f2mul(f2mul(diff, diff), cy);
            float a0, a1; upk(arg, a0, a1);
            const ull e = pk(ex2f(a0), ex2f(a1));       // exp(-diff^2*ig2)
            srbf = f2add(srbf, e);
            s1 = f2fma(e, cz, s1);
            const ull p = f2mul(diff, e);
            sd = f2fma(p, cy, sd);                      // log2e/2 * sum drbf
            s2 = f2fma(p, cw, s2);                      // sum drbf * w
        }
        float sA, sB; upk(srbf, sA, sB);
        const ull rinv = pk(__fdividef(1.f, EPSF + sA), __fdividef(1.f, EPSF + sB));
        const ull q  = f2mul(s1, rinv);                 // kernels . w
        ull fm = f2add(q, C2);                          // force magnitude
        const ull qt = f2mul(q, f2mul(kTLN2, sd));      // q * 2*sd_true
        ull dfm = f2mul(f2fma(qt, kM1, s2), rinv);      // (s2 - q*2*sd)*rinv
        const ull mm = pk((j1 != i) ? 1.f : 0.f, (j2 != i) ? 1.f : 0.f);
        fm  = f2mul(fm, mm);
        dfm = f2mul(dfm, mm);
        fx2 = f2fma(dxp, fm, fx2);
        fy2 = f2fma(dyp, fm, fy2);
        fz2 = f2fma(dzp, fm, fz2);
        dv2 = f2fma(fm, kThree, dv2);
        dv2 = f2fma(dp, dfm, dv2);
    }

    float l0, l1;
    upk(fx2, l0, l1); float fx = l0 + l1;
    upk(fy2, l0, l1); float fy = l0 + l1;
    upk(fz2, l0, l1); float fz = l0 + l1;
    upk(dv2, l0, l1); float dv = l0 + l1;

    #pragma unroll
    for (int o = 16; o > 0; o >>= 1) {
        fx += __shfl_down_sync(0xffffffffu, fx, o);
        fy += __shfl_down_sync(0xffffffffu, fy, o);
        fz += __shfl_down_sync(0xffffffffu, fz, o);
        dv += __shfl_down_sync(0xffffffffu, dv, o);
    }
    if (lane == 0) {
        f_out[b * N_PART * 3 + i * 3 + 0] = fx;
        f_out[b * N_PART * 3 + i * 3 + 1] = fy;
        f_out[b * N_PART * 3 + i * 3 + 2] = fz;
        atomicAdd(&div_out[b], -dv);   // reference returns -divergence
    }
}

extern "C" void kernel_launch(void* const* d_in, const int* in_sizes, int n_in,
                              void* d_out, int out_size) {
    const float* t     = (const float*)d_in[0];
    const float* x     = (const float*)d_in[1];
    const float* mus   = (const float*)d_in[2];
    const float* nlg   = (const float*)d_in[3];
    const float* mus_t = (const float*)d_in[4];
    const float* nlg_t = (const float*)d_in[5];
    const float* W     = (const float*)d_in[6];
    const float* bias  = (const float*)d_in[7];
    const float* imp   = (const float*)d_in[8];

    float* out = (float*)d_out;
    float* div_out = out + (out_size - NB);   // forces first, then -divergence per batch

    prep_kernel<<<1, 32>>>(t, mus, nlg, mus_t, nlg_t, W, bias, imp, div_out);
    force_kernel<<<dim3(N_PART / 4, NB), 128>>>(x, out, div_out);
}

// round 12
// speedup vs baseline: 1.4002x; 1.4002x over previous
#include <cuda_runtime.h>

#define N_PART 512
#define NK 32
#define NT 10
#define NB 8
#define EPSF 1e-6f
#define LOG2E 1.4426950408889634f
#define TWO_LN2 1.3862943611198906f

// Per-k folded constants: {mu_k, -ig2_k*log2e, w_eff_k, -2*ig2_k*w_eff_k}
__device__ float4 g_cK[NK];
__device__ float g_C;

__device__ __forceinline__ float ex2f(float x) {
    float r; asm("ex2.approx.f32 %0, %1;" : "=f"(r) : "f"(x)); return r;
}
__device__ __forceinline__ float sqrt_ap(float x) {
    float r; asm("sqrt.approx.f32 %0, %1;" : "=f"(r) : "f"(x)); return r;
}

__global__ void prep_kernel(const float* __restrict__ t,
                            const float* __restrict__ mus,
                            const float* __restrict__ nlg,
                            const float* __restrict__ mus_t,
                            const float* __restrict__ nlg_t,
                            const float* __restrict__ W,
                            const float* __restrict__ bias,
                            const float* __restrict__ imp,
                            float* __restrict__ out, int out_total) {
    __shared__ float strbf[NT];
    const int tid = threadIdx.x;
    // Zero the whole output (forces + divergence) so force_kernel can be all-atomic.
    for (int idx = tid; idx < out_total; idx += 256) out[idx] = 0.f;

    if (tid == 0) {
        float tt = t[0];
        float rb[NT];
        float s = 0.f;
        for (int i = 0; i < NT; i++) {
            float g = expf(nlg_t[i]);
            float ig2 = g * g;
            float diff = tt - mus_t[i];
            float e = expf(-diff * diff * ig2);
            rb[i] = e;
            s += e;
        }
        float inv = 1.f / (EPSF + s);
        for (int i = 0; i < NT; i++) strbf[i] = rb[i] * inv;
    }
    __syncthreads();
    if (tid < NK) {
        const int k = tid;
        float w = 0.f;
        for (int ti = 0; ti < NT; ti++) w += W[k * NT + ti] * strbf[ti];
        float g = expf(nlg[k]);
        float ig2 = g * g;
        g_cK[k] = make_float4(mus[k], -ig2 * LOG2E, w, -2.f * ig2 * w);
        float cp = imp[k] * imp[k] * w;
        #pragma unroll
        for (int o = 16; o > 0; o >>= 1) cp += __shfl_down_sync(0xffffffffu, cp, o);
        if (k == 0) {
            float bb = 0.f;
            for (int ti = 0; ti < NT; ti++) bb += bias[ti] * strbf[ti];
            g_C = bb + cp;
        }
    }
}

__global__ __launch_bounds__(128, 6) void force_kernel(const float* __restrict__ x,
                                                       float* __restrict__ f_out,
                                                       float* __restrict__ div_out) {
    __shared__ float sx[N_PART * 3];
    __shared__ float4 sc[NK];
    const int b = blockIdx.y;
    const int tid = threadIdx.x;

    for (int idx = tid; idx < N_PART * 3; idx += 128)
        sx[idx] = x[b * N_PART * 3 + idx];
    if (tid < NK) sc[tid] = g_cK[tid];
    __syncthreads();

    const float C = g_C;
    const int warp = tid >> 5;
    const int lane = tid & 31;
    const int i = blockIdx.x * 4 + warp;
    float* fb = f_out + b * N_PART * 3;

    const float xi0 = sx[i * 3 + 0];
    const float xi1 = sx[i * 3 + 1];
    const float xi2 = sx[i * 3 + 2];

    float fx = 0.f, fy = 0.f, fz = 0.f, dv = 0.f;

    // Symmetric pairing over the ring offset delta = (j - i) mod 512.
    // delta in [1,255]: owned by i. delta == 256: owned by the i < 256 side.
    #pragma unroll 1
    for (int jj = 0; jj < 8; jj++) {
        const int delta = 1 + lane + jj * 32;
        const int j = (i + delta) & (N_PART - 1);
        const float dx = xi0 - sx[j * 3 + 0];
        const float dy = xi1 - sx[j * 3 + 1];
        const float dz = xi2 - sx[j * 3 + 2];
        const float d = sqrt_ap(fmaf(dx, dx, fmaf(dy, dy, fmaf(dz, dz, EPSF))));

        float srbf = 0.f, s1 = 0.f, sd = 0.f, s2 = 0.f;
        #pragma unroll 8
        for (int k = 0; k < NK; k++) {
            const float4 c = sc[k];
            const float diff = d - c.x;              // d - mu
            const float e = ex2f(diff * diff * c.y); // exp(-diff^2*ig2) via ex2
            srbf += e;
            s1 = fmaf(e, c.z, s1);                   // sum e * w
            const float p = diff * e;
            sd = fmaf(p, c.y, sd);                   // log2e * (1/2) * sum drbf
            s2 = fmaf(p, c.w, s2);                   // sum drbf * w
        }
        const float rinv = __fdividef(1.f, EPSF + srbf);
        const float q = s1 * rinv;                   // kernels . w
        float fm = q + C;
        float dfm = (s2 - q * (TWO_LN2 * sd)) * rinv;
        // delta == 256 is seen by both sides; keep only the i < 256 owner.
        const float m = (delta == 256 && i >= 256) ? 0.f : 1.f;
        fm *= m;
        dfm *= m;
        const float gx = dx * fm, gy = dy * fm, gz = dz * fm;
        fx += gx; fy += gy; fz += gz;
        dv += fmaf(d, dfm, 3.f * fm);
        // j-side (Newton's third law): scatter -r*fm
        atomicAdd(&fb[j * 3 + 0], -gx);
        atomicAdd(&fb[j * 3 + 1], -gy);
        atomicAdd(&fb[j * 3 + 2], -gz);
    }

    #pragma unroll
    for (int o = 16; o > 0; o >>= 1) {
        fx += __shfl_down_sync(0xffffffffu, fx, o);
        fy += __shfl_down_sync(0xffffffffu, fy, o);
        fz += __shfl_down_sync(0xffffffffu, fz, o);
        dv += __shfl_down_sync(0xffffffffu, dv, o);
    }
    if (lane == 0) {
        atomicAdd(&fb[i * 3 + 0], fx);
        atomicAdd(&fb[i * 3 + 1], fy);
        atomicAdd(&fb[i * 3 + 2], fz);
        // each unordered pair stands for two ordered pairs -> x2; output is -divergence
        atomicAdd(&div_out[b], -2.f * dv);
    }
}

extern "C" void kernel_launch(void* const* d_in, const int* in_sizes, int n_in,
                              void* d_out, int out_size) {
    const float* t     = (const float*)d_in[0];
    const float* x     = (const float*)d_in[1];
    const float* mus   = (const float*)d_in[2];
    const float* nlg   = (const float*)d_in[3];
    const float* mus_t = (const float*)d_in[4];
    const float* nlg_t = (const float*)d_in[5];
    const float* W     = (const float*)d_in[6];
    const float* bias  = (const float*)d_in[7];
    const float* imp   = (const float*)d_in[8];

    float* out = (float*)d_out;
    float* div_out = out + (out_size - NB);   // forces first, then -divergence per batch

    prep_kernel<<<1, 256>>>(t, mus, nlg, mus_t, nlg_t, W, bias, imp, out, out_size);
    force_kernel<<<dim3(N_PART / 4, NB), 128>>>(x, out, div_out);
}